// round 12
// baseline (speedup 1.0000x reference)
#include <cuda_runtime.h>
#include <math.h>

#define Hh 240
#define Ww 240
#define NPIX 57600           // 240*240
#define BMAX 256

// ---------------- scratch (no cudaMalloc allowed) ----------------
// g_s1 holds only the Hermitian-unique half: kw in [0,128)
__device__ float2 g_s1[BMAX * 128 * 240];   // after K1: [b][kw<128][h]
__device__ float2 g_s2[BMAX * NPIX];        // after K2: [b][h][kw]
__device__ float2 g_tw[240];                // forward twiddles e^{-2*pi*i*j/240}

// smem row v at offset 240*v + 2*(v>>1) (bank-conflict-free; R3 analysis)
#define SMF1 (24*242)          // K1 static smem floats per array (24 rows)
#define SMF3 (16*240 + 16)     // K3 static smem floats per array
#define SMF2 (48*240 + 48)     // K2 dynamic smem floats per array (48 rows) = 11568

__device__ __forceinline__ int rowoff(int v) { return 240 * v + 2 * (v >> 1); }

// ---------------- complex helpers ----------------
__device__ __forceinline__ float2 cadd(float2 a, float2 b){ return make_float2(a.x+b.x, a.y+b.y); }
__device__ __forceinline__ float2 csub(float2 a, float2 b){ return make_float2(a.x-b.x, a.y-b.y); }
__device__ __forceinline__ float2 cmul(float2 a, float2 b){
    return make_float2(a.x*b.x - a.y*b.y, a.x*b.y + a.y*b.x);
}

// DIR = -1 forward (e^{-i}), +1 inverse (e^{+i})
template<int DIR>
__device__ __forceinline__ void dft4(float2 a[4]) {
    float2 u0 = cadd(a[0], a[2]);
    float2 u1 = csub(a[0], a[2]);
    float2 u2 = cadd(a[1], a[3]);
    float2 u3 = csub(a[1], a[3]);
    float2 j3 = make_float2((DIR < 0) ? u3.y : -u3.y, (DIR < 0) ? -u3.x : u3.x);
    a[0] = cadd(u0, u2);
    a[2] = csub(u0, u2);
    a[1] = cadd(u1, j3);
    a[3] = csub(u1, j3);
}

__device__ __constant__ float C16c[10] = {1.f,0.92387953f,0.70710678f,0.38268343f,0.f,-0.38268343f,-0.70710678f,-0.92387953f,-1.f,-0.92387953f};
__device__ __constant__ float S16c[10] = {0.f,0.38268343f,0.70710678f,0.92387953f,1.f,0.92387953f,0.70710678f,0.38268343f,0.f,-0.38268343f};
__device__ __constant__ float C15c[9] = {1.f,0.91354546f,0.66913061f,0.30901699f,-0.10452846f,-0.5f,-0.80901699f,-0.97814760f,-0.97814760f};
__device__ __constant__ float S15c[9] = {0.f,0.40673664f,0.74314483f,0.95105652f,0.99452190f,0.86602540f,0.58778525f,0.20791169f,-0.20791169f};

template<int DIR>
__device__ __forceinline__ void fft16(float2 a[16]) {
    float2 b[4][4];
#pragma unroll
    for (int n2 = 0; n2 < 4; n2++) {
        float2 t[4];
#pragma unroll
        for (int n1 = 0; n1 < 4; n1++) t[n1] = a[4*n1 + n2];
        dft4<DIR>(t);
#pragma unroll
        for (int k1 = 0; k1 < 4; k1++) {
            const int j = n2 * k1;
            float2 w = make_float2(C16c[j], (DIR < 0) ? -S16c[j] : S16c[j]);
            b[n2][k1] = cmul(t[k1], w);
        }
    }
#pragma unroll
    for (int k1 = 0; k1 < 4; k1++) {
        float2 t[4];
#pragma unroll
        for (int n2 = 0; n2 < 4; n2++) t[n2] = b[n2][k1];
        dft4<DIR>(t);
#pragma unroll
        for (int k2 = 0; k2 < 4; k2++) a[k1 + 4*k2] = t[k2];
    }
}

template<int DIR>
__device__ __forceinline__ void dft5(float2 a[5]) {
    const float c1 = 0.309016994f, s1 = 0.951056516f;
    const float c2 = -0.809016994f, s2 = 0.587785252f;
    float2 a0 = a[0];
    float2 t1 = cadd(a[1], a[4]);
    float2 t2 = cadd(a[2], a[3]);
    float2 t3 = csub(a[1], a[4]);
    float2 t4 = csub(a[2], a[3]);
    float2 m1 = make_float2(a0.x + c1*t1.x + c2*t2.x, a0.y + c1*t1.y + c2*t2.y);
    float2 m2 = make_float2(a0.x + c2*t1.x + c1*t2.x, a0.y + c2*t1.y + c1*t2.y);
    float2 p1 = make_float2(s1*t3.x + s2*t4.x, s1*t3.y + s2*t4.y);
    float2 p2 = make_float2(s2*t3.x - s1*t4.x, s2*t3.y - s1*t4.y);
    float2 j1 = make_float2((DIR < 0) ? p1.y : -p1.y, (DIR < 0) ? -p1.x : p1.x);
    float2 j2 = make_float2((DIR < 0) ? p2.y : -p2.y, (DIR < 0) ? -p2.x : p2.x);
    a[0] = make_float2(a0.x + t1.x + t2.x, a0.y + t1.y + t2.y);
    a[1] = cadd(m1, j1);
    a[4] = csub(m1, j1);
    a[2] = cadd(m2, j2);
    a[3] = csub(m2, j2);
}

template<int DIR>
__device__ __forceinline__ void dft3(float2 a[3]) {
    const float s3 = 0.866025404f;
    float2 a0 = a[0];
    float2 t1 = cadd(a[1], a[2]);
    float2 t2 = csub(a[1], a[2]);
    float2 m = make_float2(a0.x - 0.5f*t1.x, a0.y - 0.5f*t1.y);
    float2 jt = make_float2((DIR < 0) ? s3*t2.y : -s3*t2.y, (DIR < 0) ? -s3*t2.x : s3*t2.x);
    a[0] = make_float2(a0.x + t1.x, a0.y + t1.y);
    a[1] = cadd(m, jt);
    a[2] = csub(m, jt);
}

template<int DIR>
__device__ __forceinline__ void fft15(float2 a[15]) {
    float2 c[3][5];
#pragma unroll
    for (int m2 = 0; m2 < 3; m2++) {
        float2 t[5];
#pragma unroll
        for (int m1 = 0; m1 < 5; m1++) t[m1] = a[3*m1 + m2];
        dft5<DIR>(t);
#pragma unroll
        for (int p1 = 0; p1 < 5; p1++) {
            const int j = m2 * p1;
            float2 w = make_float2(C15c[j], (DIR < 0) ? -S15c[j] : S15c[j]);
            c[m2][p1] = cmul(t[p1], w);
        }
    }
#pragma unroll
    for (int p1 = 0; p1 < 5; p1++) {
        float2 t[3] = {c[0][p1], c[1][p1], c[2][p1]};
        dft3<DIR>(t);
        a[p1]      = t[0];
        a[p1 + 5]  = t[1];
        a[p1 + 10] = t[2];
    }
}

// ---- stage pieces (warp-private rows; only __syncwarp) ----

template<int DIR>
__device__ __forceinline__ void stage1_tail(float2 a[16], float* re, float* im, int t) {
#pragma unroll
    for (int k1 = 1; k1 < 16; k1++) {
        float2 w = __ldg(&g_tw[t * k1]);
        if (DIR > 0) w.y = -w.y;
        a[k1] = cmul(a[k1], w);
    }
#pragma unroll
    for (int k1 = 0; k1 < 16; k1++) { re[15*k1 + t] = a[k1].x; im[15*k1 + t] = a[k1].y; }
}

template<int DIR>
__device__ __forceinline__ void stage1_s(float* re, float* im, int t) {
    if (t < 15) {
        float2 a[16];
#pragma unroll
        for (int n1 = 0; n1 < 16; n1++) { a[n1].x = re[15*n1 + t]; a[n1].y = im[15*n1 + t]; }
        fft16<DIR>(a);
        stage1_tail<DIR>(a, re, im, t);
    }
    __syncwarp();
}

// stage 1, complex inputs from global; STREAM=true -> evict-first (last use)
template<int DIR, bool STREAM>
__device__ __forceinline__ void stage1_g(const float2* __restrict__ gsrc,
                                         float* re, float* im, int t) {
    if (t < 15) {
        float2 a[16];
#pragma unroll
        for (int n1 = 0; n1 < 16; n1++)
            a[n1] = STREAM ? __ldcs(&gsrc[15*n1 + t]) : __ldg(&gsrc[15*n1 + t]);
        fft16<DIR>(a);
        stage1_tail<DIR>(a, re, im, t);
    }
    __syncwarp();
}

// stage 1, PACKED pair of real rows (a + i*b) loaded directly from global
__device__ __forceinline__ void stage1_g_pair(const float* __restrict__ ra,
                                              const float* __restrict__ rb,
                                              float* re, float* im, int t) {
    if (t < 15) {
        float2 a[16];
#pragma unroll
        for (int n1 = 0; n1 < 16; n1++)
            a[n1] = make_float2(__ldcs(&ra[15*n1 + t]), __ldcs(&rb[15*n1 + t]));
        fft16<-1>(a);
        stage1_tail<-1>(a, re, im, t);
    }
    __syncwarp();
}

template<int DIR>
__device__ __forceinline__ void stage2(float* re, float* im, int t) {
    float2 b[15];
#pragma unroll
    for (int n2 = 0; n2 < 15; n2++) { b[n2].x = re[15*t + n2]; b[n2].y = im[15*t + n2]; }
    fft15<DIR>(b);
    __syncwarp();
    const float sc = (DIR > 0) ? (1.0f / 240.0f) : 1.0f;
#pragma unroll
    for (int j = 0; j < 15; j++) { re[t + 16*j] = b[j].x * sc; im[t + 16*j] = b[j].y * sc; }
    __syncwarp();
}

// stage 2 inverse + magnitude, stored DIRECTLY to global (row-contiguous dst)
__device__ __forceinline__ void stage2_mag_g(const float* re, const float* im, int t,
                                             float* __restrict__ gdst) {
    float2 b[15];
#pragma unroll
    for (int n2 = 0; n2 < 15; n2++) { b[n2].x = re[15*t + n2]; b[n2].y = im[15*t + n2]; }
    fft15<1>(b);
    const float sc = 1.0f / 240.0f;
#pragma unroll
    for (int j = 0; j < 15; j++)
        gdst[t + 16*j] = sc * sqrtf(b[j].x * b[j].x + b[j].y * b[j].y);
}

// ---------------- kernels ----------------
__global__ void init_tw_kernel() {
    int j = threadIdx.x;
    if (j < 240) {
        float s, c;
        sincosf(-6.283185307179586f * (float)j / 240.0f, &s, &c);
        g_tw[j] = make_float2(c, s);
    }
}

// K1: packed forward row FFTs of real input -> g_s1[b][kw<128][h]
// 384 threads, 12 warps; warp w does packed FFTs p=2w (h=0) and p=2w+1 (h=1);
// packed FFT p covers real rows (h0+2p, h0+2p+1).  grid.x = 5 (48 rows/block).
__global__ __launch_bounds__(384) void k_rowfft(const float* __restrict__ x) {
    __shared__ float sre[SMF1], sim[SMF1];
    const int b = blockIdx.y;
    const int h0 = blockIdx.x * 48;
    const int tid = threadIdx.x;
    const int w = tid >> 5, lane = tid & 31;
    const int t = lane & 15, h = lane >> 4;
    const int p = 2 * w + h;                 // packed index 0..23

    const float* ra = x + ((size_t)b * 240 + h0 + 2 * p) * 240;
    float* re = sre + 482 * w + 240 * h;     // == sre + rowoff(p)
    float* im = sim + 482 * w + 240 * h;
    stage1_g_pair(ra, ra + 240, re, im, t);
    stage2<-1>(re, im, t);
    __syncthreads();

    // separation + transposed store: Z = FFT(a+ib) ->
    //   A[k] = (Z[k]+conj(Z[m]))/2,  B[k] = -i(Z[k]-conj(Z[m]))/2,  m=(240-k)%240
    {
        const int hh = tid % 48;
        const int kwb = tid / 48;            // 0..7
        const int pp = hh >> 1, e = hh & 1;
        const float* zr = sre + rowoff(pp);
        const float* zi = sim + rowoff(pp);
        float2* dst = g_s1 + ((size_t)b * 128) * 240 + h0 + hh;
#pragma unroll
        for (int jj = 0; jj < 16; jj++) {
            int kw = kwb * 16 + jj;          // 0..127
            int m = (kw == 0) ? 0 : 240 - kw;
            float x1 = zr[kw], y1 = zi[kw];
            float x2 = zr[m],  y2 = zi[m];
            float2 v;
            if (e == 0) v = make_float2(0.5f * (x1 + x2), 0.5f * (y1 - y2));
            else        v = make_float2(0.5f * (y1 + y2), 0.5f * (x2 - x1));
            dst[(size_t)kw * 240] = v;
        }
    }
}

// K2: warp-specialized: warps 0-7 fwd-FFT the 16 primary cols while warps 8-15
// prefetch the block's full y tile into smem (mirror rows 16-31 get mirror-y,
// staging rows 32-47 get primary-y).  Then Hermitian mirror build + combine
// (pure smem+A) + 32 column IFFTs + transposed store.  512 threads.
__global__ __launch_bounds__(512, 2) void k_colfft(const float* __restrict__ yk,
                                                   const float* __restrict__ Am) {
    extern __shared__ float dsm[];
    float* sre = dsm;
    float* sim = dsm + SMF2;
    const int b = blockIdx.y;
    const int kw0 = blockIdx.x * 16;     // blockIdx.x in [0,8) -> primaries 0..127
    const int tid = threadIdx.x;
    const int w = tid >> 5, lane = tid & 31;
    const int t = lane & 15;
    const int h = lane >> 4;

    const float* yr = yk + (size_t)b * (2 * NPIX);
    const float* yi = yr + NPIX;

    // ---- phase 1: fwd FFT (warps 0-7)  ||  y prefetch (warps 8-15) ----
    if (w < 8) {
        const int row = 2 * w + h;
        float* re = sre + rowoff(row);
        float* im = sim + rowoff(row);
        const float2* gsrc = g_s1 + ((size_t)b * 128 + kw0 + row) * 240;
        stage1_g<-1, false>(gsrc, re, im, t);    // want L2 hits from K1
        stage2<-1>(re, im, t);
    } else {
        const int u = tid - 256;             // 0..255
        const int v = u & 15;
        const int khb = u >> 4;              // 0..15
        const int kwm = (240 - (kw0 + v)) % 240;
        float* mre = sre + rowoff(16 + v);
        float* mim = sim + rowoff(16 + v);
        float* qre = sre + rowoff(32 + v);
        float* qim = sim + rowoff(32 + v);
#pragma unroll
        for (int j = 0; j < 15; j++) {
            int kh = khb + 16 * j;
            int idxm = kh * 240 + kwm;
            int idxp = kh * 240 + kw0 + v;
            mre[kh] = __ldcs(&yr[idxm]);
            mim[kh] = __ldcs(&yi[idxm]);
            qre[kh] = __ldcs(&yr[idxp]);
            qim[kh] = __ldcs(&yi[idxp]);
        }
    }
    __syncthreads();

    // ---- mirror build: row 16+v <- (1-A')*conj(rev(row v)) + prefetched y' ----
    {
        const int v = tid & 15;
        const int khb = tid >> 4;            // 0..31
        const int kwm = (240 - (kw0 + v)) % 240;
        const float* pre = sre + rowoff(v);
        const float* pim = sim + rowoff(v);
        float* mre = sre + rowoff(16 + v);
        float* mim = sim + rowoff(16 + v);
#pragma unroll
        for (int j = 0; j < 8; j++) {
            int kh = khb + 32 * j;
            if (kh < 240) {
                int s = (kh == 0) ? 0 : 240 - kh;
                float a = 1.0f - __ldg(&Am[kh * 240 + kwm]);
                mre[kh] =  pre[s] * a + mre[kh];
                mim[kh] = -pim[s] * a + mim[kh];
            }
        }
    }
    __syncthreads();

    // ---- primary combine in place (y from staging rows 32-47) ----
    {
        const int v = tid & 15;
        const int khb = tid >> 4;
        float* pre = sre + rowoff(v);
        float* pim = sim + rowoff(v);
        const float* qre = sre + rowoff(32 + v);
        const float* qim = sim + rowoff(32 + v);
#pragma unroll
        for (int j = 0; j < 8; j++) {
            int kh = khb + 32 * j;
            if (kh < 240) {
                float a = 1.0f - __ldg(&Am[kh * 240 + kw0 + v]);
                pre[kh] = pre[kh] * a + qre[kh];
                pim[kh] = pim[kh] * a + qim[kh];
            }
        }
    }
    __syncthreads();

    // ---- inverse FFT of all 32 rows: warp w owns rows 2w, 2w+1 ----
    {
        const int v = 2 * w + h;
        float* re = sre + rowoff(v);
        float* im = sim + rowoff(v);
        stage1_s<1>(re, im, t);
        stage2<1>(re, im, t);
    }
    __syncthreads();

    // ---- transposed store: primaries always; mirrors only if kwm >= 128
    // (masks the redundant overlap -> each g_s2 word written exactly once) ----
    {
        const int v = tid & 15;
        const int hb = tid >> 4;             // 0..31
        const float* pre = sre + rowoff(v);
        const float* pim = sim + rowoff(v);
        const float* mre = sre + rowoff(16 + v);
        const float* mim = sim + rowoff(16 + v);
        const int kwm = (240 - (kw0 + v)) % 240;
        float2* dstP = g_s2 + (size_t)b * NPIX + kw0 + v;
        float2* dstM = g_s2 + (size_t)b * NPIX + kwm;
        const bool storeM = (kwm >= 128);
#pragma unroll
        for (int j = 0; j < 8; j++) {
            int hh = hb + 32 * j;
            if (hh < 240) {
                dstP[(size_t)hh * 240] = make_float2(pre[hh], pim[hh]);
                if (storeM) dstM[(size_t)hh * 240] = make_float2(mre[hh], mim[hh]);
            }
        }
    }
}

// K3: inverse row FFTs + abs -> out[b][h][w]  (zero staging, no block sync)
__global__ __launch_bounds__(256) void k_invrow(float* __restrict__ out) {
    __shared__ float sre[SMF3], sim[SMF3];
    const int b = blockIdx.y;
    const int h0 = blockIdx.x * 16;
    const int tid = threadIdx.x;
    const int w = tid >> 5, lane = tid & 31;
    const int t = lane & 15, h = lane >> 4;

    float* re = sre + 482 * w + 240 * h;
    float* im = sim + 482 * w + 240 * h;

    const float2* gsrc = g_s2 + ((size_t)b * 240 + h0 + 2 * w + h) * 240;
    stage1_g<1, true>(gsrc, re, im, t);      // last use -> evict-first

    float* ob = out + ((size_t)b * 240 + h0 + 2 * w + h) * 240;
    stage2_mag_g(re, im, t, ob);
}

extern "C" void kernel_launch(void* const* d_in, const int* in_sizes, int n_in,
                              void* d_out, int out_size) {
    const float* T2_Gen    = (const float*)d_in[0];  // [B,1,240,240] f32
    const float* underT2_K = (const float*)d_in[1];  // [B,2,240,240] f32
    const float* A         = (const float*)d_in[2];  // [240,240] f32
    float* out = (float*)d_out;

    int B = in_sizes[0] / NPIX;   // 256

    const int k2_smem = 2 * SMF2 * (int)sizeof(float);   // 92,544 B
    cudaFuncSetAttribute(k_colfft, cudaFuncAttributeMaxDynamicSharedMemorySize, k2_smem);

    init_tw_kernel<<<1, 256>>>();
    k_rowfft<<<dim3(5, B), 384>>>(T2_Gen);
    k_colfft<<<dim3(8, B), 512, k2_smem>>>(underT2_K, A);
    k_invrow<<<dim3(15, B), 256>>>(out);
}

// round 13
// speedup vs baseline: 1.1278x; 1.1278x over previous
#include <cuda_runtime.h>
#include <cuda_fp16.h>
#include <math.h>

#define Hh 240
#define Ww 240
#define NPIX 57600           // 240*240
#define BMAX 256

// ---------------- scratch (no cudaMalloc allowed) ----------------
// g_s1 holds only the Hermitian-unique half: kw in [0,128)
__device__ float2 g_s1[BMAX * 128 * 240];   // after K1: [b][kw<128][h]  fp32
__device__ __half2 g_s2h[BMAX * NPIX];      // after K2: [b][h][kw]  (re,im) fp16
__device__ float2 g_tw[240];                // forward twiddles e^{-2*pi*i*j/240}

// smem row v at offset 240*v + 2*(v>>1) (bank-conflict-free; R3 analysis)
#define SMF1 (24*242)          // K1 static smem floats per array (24 rows)
#define SMF3 (16*240 + 16)     // K3 static smem floats per array
#define SMF2 (32*240 + 32)     // K2 dynamic smem floats per array = 7712

__device__ __forceinline__ int rowoff(int v) { return 240 * v + 2 * (v >> 1); }

// ---------------- complex helpers ----------------
__device__ __forceinline__ float2 cadd(float2 a, float2 b){ return make_float2(a.x+b.x, a.y+b.y); }
__device__ __forceinline__ float2 csub(float2 a, float2 b){ return make_float2(a.x-b.x, a.y-b.y); }
__device__ __forceinline__ float2 cmul(float2 a, float2 b){
    return make_float2(a.x*b.x - a.y*b.y, a.x*b.y + a.y*b.x);
}

// DIR = -1 forward (e^{-i}), +1 inverse (e^{+i})
template<int DIR>
__device__ __forceinline__ void dft4(float2 a[4]) {
    float2 u0 = cadd(a[0], a[2]);
    float2 u1 = csub(a[0], a[2]);
    float2 u2 = cadd(a[1], a[3]);
    float2 u3 = csub(a[1], a[3]);
    float2 j3 = make_float2((DIR < 0) ? u3.y : -u3.y, (DIR < 0) ? -u3.x : u3.x);
    a[0] = cadd(u0, u2);
    a[2] = csub(u0, u2);
    a[1] = cadd(u1, j3);
    a[3] = csub(u1, j3);
}

__device__ __constant__ float C16c[10] = {1.f,0.92387953f,0.70710678f,0.38268343f,0.f,-0.38268343f,-0.70710678f,-0.92387953f,-1.f,-0.92387953f};
__device__ __constant__ float S16c[10] = {0.f,0.38268343f,0.70710678f,0.92387953f,1.f,0.92387953f,0.70710678f,0.38268343f,0.f,-0.38268343f};
__device__ __constant__ float C15c[9] = {1.f,0.91354546f,0.66913061f,0.30901699f,-0.10452846f,-0.5f,-0.80901699f,-0.97814760f,-0.97814760f};
__device__ __constant__ float S15c[9] = {0.f,0.40673664f,0.74314483f,0.95105652f,0.99452190f,0.86602540f,0.58778525f,0.20791169f,-0.20791169f};

template<int DIR>
__device__ __forceinline__ void fft16(float2 a[16]) {
    float2 b[4][4];
#pragma unroll
    for (int n2 = 0; n2 < 4; n2++) {
        float2 t[4];
#pragma unroll
        for (int n1 = 0; n1 < 4; n1++) t[n1] = a[4*n1 + n2];
        dft4<DIR>(t);
#pragma unroll
        for (int k1 = 0; k1 < 4; k1++) {
            const int j = n2 * k1;
            float2 w = make_float2(C16c[j], (DIR < 0) ? -S16c[j] : S16c[j]);
            b[n2][k1] = cmul(t[k1], w);
        }
    }
#pragma unroll
    for (int k1 = 0; k1 < 4; k1++) {
        float2 t[4];
#pragma unroll
        for (int n2 = 0; n2 < 4; n2++) t[n2] = b[n2][k1];
        dft4<DIR>(t);
#pragma unroll
        for (int k2 = 0; k2 < 4; k2++) a[k1 + 4*k2] = t[k2];
    }
}

template<int DIR>
__device__ __forceinline__ void dft5(float2 a[5]) {
    const float c1 = 0.309016994f, s1 = 0.951056516f;
    const float c2 = -0.809016994f, s2 = 0.587785252f;
    float2 a0 = a[0];
    float2 t1 = cadd(a[1], a[4]);
    float2 t2 = cadd(a[2], a[3]);
    float2 t3 = csub(a[1], a[4]);
    float2 t4 = csub(a[2], a[3]);
    float2 m1 = make_float2(a0.x + c1*t1.x + c2*t2.x, a0.y + c1*t1.y + c2*t2.y);
    float2 m2 = make_float2(a0.x + c2*t1.x + c1*t2.x, a0.y + c2*t1.y + c1*t2.y);
    float2 p1 = make_float2(s1*t3.x + s2*t4.x, s1*t3.y + s2*t4.y);
    float2 p2 = make_float2(s2*t3.x - s1*t4.x, s2*t3.y - s1*t4.y);
    float2 j1 = make_float2((DIR < 0) ? p1.y : -p1.y, (DIR < 0) ? -p1.x : p1.x);
    float2 j2 = make_float2((DIR < 0) ? p2.y : -p2.y, (DIR < 0) ? -p2.x : p2.x);
    a[0] = make_float2(a0.x + t1.x + t2.x, a0.y + t1.y + t2.y);
    a[1] = cadd(m1, j1);
    a[4] = csub(m1, j1);
    a[2] = cadd(m2, j2);
    a[3] = csub(m2, j2);
}

template<int DIR>
__device__ __forceinline__ void dft3(float2 a[3]) {
    const float s3 = 0.866025404f;
    float2 a0 = a[0];
    float2 t1 = cadd(a[1], a[2]);
    float2 t2 = csub(a[1], a[2]);
    float2 m = make_float2(a0.x - 0.5f*t1.x, a0.y - 0.5f*t1.y);
    float2 jt = make_float2((DIR < 0) ? s3*t2.y : -s3*t2.y, (DIR < 0) ? -s3*t2.x : s3*t2.x);
    a[0] = make_float2(a0.x + t1.x, a0.y + t1.y);
    a[1] = cadd(m, jt);
    a[2] = csub(m, jt);
}

template<int DIR>
__device__ __forceinline__ void fft15(float2 a[15]) {
    float2 c[3][5];
#pragma unroll
    for (int m2 = 0; m2 < 3; m2++) {
        float2 t[5];
#pragma unroll
        for (int m1 = 0; m1 < 5; m1++) t[m1] = a[3*m1 + m2];
        dft5<DIR>(t);
#pragma unroll
        for (int p1 = 0; p1 < 5; p1++) {
            const int j = m2 * p1;
            float2 w = make_float2(C15c[j], (DIR < 0) ? -S15c[j] : S15c[j]);
            c[m2][p1] = cmul(t[p1], w);
        }
    }
#pragma unroll
    for (int p1 = 0; p1 < 5; p1++) {
        float2 t[3] = {c[0][p1], c[1][p1], c[2][p1]};
        dft3<DIR>(t);
        a[p1]      = t[0];
        a[p1 + 5]  = t[1];
        a[p1 + 10] = t[2];
    }
}

// ---- stage pieces (warp-private rows; only __syncwarp) ----

template<int DIR>
__device__ __forceinline__ void stage1_tail(float2 a[16], float* re, float* im, int t) {
#pragma unroll
    for (int k1 = 1; k1 < 16; k1++) {
        float2 w = __ldg(&g_tw[t * k1]);
        if (DIR > 0) w.y = -w.y;
        a[k1] = cmul(a[k1], w);
    }
#pragma unroll
    for (int k1 = 0; k1 < 16; k1++) { re[15*k1 + t] = a[k1].x; im[15*k1 + t] = a[k1].y; }
}

template<int DIR>
__device__ __forceinline__ void stage1_s(float* re, float* im, int t) {
    if (t < 15) {
        float2 a[16];
#pragma unroll
        for (int n1 = 0; n1 < 16; n1++) { a[n1].x = re[15*n1 + t]; a[n1].y = im[15*n1 + t]; }
        fft16<DIR>(a);
        stage1_tail<DIR>(a, re, im, t);
    }
    __syncwarp();
}

// stage 1, complex fp32 inputs from global (default caching -> L2 reuse)
template<int DIR>
__device__ __forceinline__ void stage1_g(const float2* __restrict__ gsrc,
                                         float* re, float* im, int t) {
    if (t < 15) {
        float2 a[16];
#pragma unroll
        for (int n1 = 0; n1 < 16; n1++) a[n1] = __ldg(&gsrc[15*n1 + t]);
        fft16<DIR>(a);
        stage1_tail<DIR>(a, re, im, t);
    }
    __syncwarp();
}

// stage 1, complex fp16 inputs from global (g_s2h; L2-resident, last use)
__device__ __forceinline__ void stage1_gh(const __half2* __restrict__ gsrc,
                                          float* re, float* im, int t) {
    if (t < 15) {
        float2 a[16];
#pragma unroll
        for (int n1 = 0; n1 < 16; n1++) a[n1] = __half22float2(__ldcs(&gsrc[15*n1 + t]));
        fft16<1>(a);
        stage1_tail<1>(a, re, im, t);
    }
    __syncwarp();
}

// stage 1, PACKED pair of real rows (a + i*b) loaded directly from global
__device__ __forceinline__ void stage1_g_pair(const float* __restrict__ ra,
                                              const float* __restrict__ rb,
                                              float* re, float* im, int t) {
    if (t < 15) {
        float2 a[16];
#pragma unroll
        for (int n1 = 0; n1 < 16; n1++)
            a[n1] = make_float2(__ldcs(&ra[15*n1 + t]), __ldcs(&rb[15*n1 + t]));
        fft16<-1>(a);
        stage1_tail<-1>(a, re, im, t);
    }
    __syncwarp();
}

template<int DIR>
__device__ __forceinline__ void stage2(float* re, float* im, int t) {
    float2 b[15];
#pragma unroll
    for (int n2 = 0; n2 < 15; n2++) { b[n2].x = re[15*t + n2]; b[n2].y = im[15*t + n2]; }
    fft15<DIR>(b);
    __syncwarp();
    const float sc = (DIR > 0) ? (1.0f / 240.0f) : 1.0f;
#pragma unroll
    for (int j = 0; j < 15; j++) { re[t + 16*j] = b[j].x * sc; im[t + 16*j] = b[j].y * sc; }
    __syncwarp();
}

// stage 2 inverse + magnitude, stored DIRECTLY to global (row-contiguous dst)
__device__ __forceinline__ void stage2_mag_g(const float* re, const float* im, int t,
                                             float* __restrict__ gdst) {
    float2 b[15];
#pragma unroll
    for (int n2 = 0; n2 < 15; n2++) { b[n2].x = re[15*t + n2]; b[n2].y = im[15*t + n2]; }
    fft15<1>(b);
    const float sc = 1.0f / 240.0f;
#pragma unroll
    for (int j = 0; j < 15; j++)
        gdst[t + 16*j] = sc * sqrtf(b[j].x * b[j].x + b[j].y * b[j].y);
}

// ---------------- kernels ----------------
__global__ void init_tw_kernel() {
    int j = threadIdx.x;
    if (j < 240) {
        float s, c;
        sincosf(-6.283185307179586f * (float)j / 240.0f, &s, &c);
        g_tw[j] = make_float2(c, s);
    }
}

// K1: packed forward row FFTs of real input -> g_s1[b][kw<128][h]
// 384 threads, 12 warps; warp w does packed FFTs p=2w (h=0) and p=2w+1 (h=1);
// packed FFT p covers real rows (h0+2p, h0+2p+1).  grid.x = 5 (48 rows/block).
__global__ __launch_bounds__(384) void k_rowfft(const float* __restrict__ x) {
    __shared__ float sre[SMF1], sim[SMF1];
    const int b = blockIdx.y;
    const int h0 = blockIdx.x * 48;
    const int tid = threadIdx.x;
    const int w = tid >> 5, lane = tid & 31;
    const int t = lane & 15, h = lane >> 4;
    const int p = 2 * w + h;                 // packed index 0..23

    const float* ra = x + ((size_t)b * 240 + h0 + 2 * p) * 240;
    float* re = sre + 482 * w + 240 * h;     // == sre + rowoff(p)
    float* im = sim + 482 * w + 240 * h;
    stage1_g_pair(ra, ra + 240, re, im, t);
    stage2<-1>(re, im, t);
    __syncthreads();

    // separation + transposed store: Z = FFT(a+ib) ->
    //   A[k] = (Z[k]+conj(Z[m]))/2,  B[k] = -i(Z[k]-conj(Z[m]))/2,  m=(240-k)%240
    {
        const int hh = tid % 48;
        const int kwb = tid / 48;            // 0..7
        const int pp = hh >> 1, e = hh & 1;
        const float* zr = sre + rowoff(pp);
        const float* zi = sim + rowoff(pp);
        float2* dst = g_s1 + ((size_t)b * 128) * 240 + h0 + hh;
#pragma unroll
        for (int jj = 0; jj < 16; jj++) {
            int kw = kwb * 16 + jj;          // 0..127
            int m = (kw == 0) ? 0 : 240 - kw;
            float x1 = zr[kw], y1 = zi[kw];
            float x2 = zr[m],  y2 = zi[m];
            float2 v;
            if (e == 0) v = make_float2(0.5f * (x1 + x2), 0.5f * (y1 - y2));
            else        v = make_float2(0.5f * (y1 + y2), 0.5f * (x2 - x1));
            dst[(size_t)kw * 240] = v;
        }
    }
}

// K2: fwd column FFT of 16 primary cols (warps 0-7, deduped) + Hermitian mirror
// reconstruction + combine + 32 column IFFTs (all 16 warps).  512 threads.
__global__ __launch_bounds__(512, 2) void k_colfft(const float* __restrict__ yk,
                                                   const float* __restrict__ Am) {
    extern __shared__ float dsm[];
    float* sre = dsm;
    float* sim = dsm + SMF2;
    const int b = blockIdx.y;
    const int kw0 = blockIdx.x * 16;     // blockIdx.x in [0,8) -> primaries 0..127
    const int tid = threadIdx.x;
    const int w = tid >> 5, lane = tid & 31;
    const int t = lane & 15;
    const int h = lane >> 4;

    // ---- forward FFT of 16 primary columns: warps 0-7 own rows 2w, 2w+1;
    // warps 8-15 go straight to the barrier (no duplicated loads/FLOPs) ----
    if (w < 8) {
        const int row = 2 * w + h;
        float* re = sre + rowoff(row);
        float* im = sim + rowoff(row);
        const float2* gsrc = g_s1 + ((size_t)b * 128 + kw0 + row) * 240;
        stage1_g<-1>(gsrc, re, im, t);       // want L2 hits from K1
        stage2<-1>(re, im, t);
    }
    __syncthreads();

    const float* yr = yk + (size_t)b * (2 * NPIX);
    const float* yi = yr + NPIX;

    // ---- mirror build + combine: row 16+v <- (1-A')*conj(rev(row v)) + y' ----
    {
        const int v = tid & 15;
        const int khb = tid >> 4;            // 0..31
        const int kwm = (240 - (kw0 + v)) % 240;
        const float* pre = sre + rowoff(v);
        const float* pim = sim + rowoff(v);
        float* mre = sre + rowoff(16 + v);
        float* mim = sim + rowoff(16 + v);
#pragma unroll
        for (int j = 0; j < 8; j++) {
            int kh = khb + 32 * j;
            if (kh < 240) {
                int s = (kh == 0) ? 0 : 240 - kh;
                int idx = kh * 240 + kwm;
                float a = 1.0f - __ldg(&Am[idx]);
                mre[kh] =  pre[s] * a + __ldcs(&yr[idx]);
                mim[kh] = -pim[s] * a + __ldcs(&yi[idx]);
            }
        }
    }
    __syncthreads();

    // ---- primary combine in place ----
    {
        const int v = tid & 15;
        const int khb = tid >> 4;
        float* pre = sre + rowoff(v);
        float* pim = sim + rowoff(v);
#pragma unroll
        for (int j = 0; j < 8; j++) {
            int kh = khb + 32 * j;
            if (kh < 240) {
                int idx = kh * 240 + kw0 + v;
                float a = 1.0f - __ldg(&Am[idx]);
                pre[kh] = pre[kh] * a + __ldcs(&yr[idx]);
                pim[kh] = pim[kh] * a + __ldcs(&yi[idx]);
            }
        }
    }
    __syncthreads();

    // ---- inverse FFT of all 32 rows: warp w owns rows 2w, 2w+1 ----
    {
        const int v = 2 * w + h;
        float* re = sre + rowoff(v);
        float* im = sim + rowoff(v);
        stage1_s<1>(re, im, t);
        stage2<1>(re, im, t);
    }
    __syncthreads();

    // ---- transposed fp16 store: primaries always; mirrors only if kwm >= 128
    // (masks the redundant overlap -> each g_s2h word written exactly once) ----
    {
        const int v = tid & 15;
        const int hb = tid >> 4;             // 0..31
        const float* pre = sre + rowoff(v);
        const float* pim = sim + rowoff(v);
        const float* mre = sre + rowoff(16 + v);
        const float* mim = sim + rowoff(16 + v);
        const int kwm = (240 - (kw0 + v)) % 240;
        __half2* dstP = g_s2h + (size_t)b * NPIX + kw0 + v;
        __half2* dstM = g_s2h + (size_t)b * NPIX + kwm;
        const bool storeM = (kwm >= 128);
#pragma unroll
        for (int j = 0; j < 8; j++) {
            int hh = hb + 32 * j;
            if (hh < 240) {
                dstP[(size_t)hh * 240] = __floats2half2_rn(pre[hh], pim[hh]);
                if (storeM) dstM[(size_t)hh * 240] = __floats2half2_rn(mre[hh], mim[hh]);
            }
        }
    }
}

// K3: inverse row FFTs + abs -> out[b][h][w]  (zero staging, no block sync)
__global__ __launch_bounds__(256) void k_invrow(float* __restrict__ out) {
    __shared__ float sre[SMF3], sim[SMF3];
    const int b = blockIdx.y;
    const int h0 = blockIdx.x * 16;
    const int tid = threadIdx.x;
    const int w = tid >> 5, lane = tid & 31;
    const int t = lane & 15, h = lane >> 4;

    float* re = sre + 482 * w + 240 * h;
    float* im = sim + 482 * w + 240 * h;

    const __half2* gsrc = g_s2h + ((size_t)b * 240 + h0 + 2 * w + h) * 240;
    stage1_gh(gsrc, re, im, t);              // L2-resident fp16, last use

    float* ob = out + ((size_t)b * 240 + h0 + 2 * w + h) * 240;
    stage2_mag_g(re, im, t, ob);
}

extern "C" void kernel_launch(void* const* d_in, const int* in_sizes, int n_in,
                              void* d_out, int out_size) {
    const float* T2_Gen    = (const float*)d_in[0];  // [B,1,240,240] f32
    const float* underT2_K = (const float*)d_in[1];  // [B,2,240,240] f32
    const float* A         = (const float*)d_in[2];  // [240,240] f32
    float* out = (float*)d_out;

    int B = in_sizes[0] / NPIX;   // 256

    const int k2_smem = 2 * SMF2 * (int)sizeof(float);   // 61,696 B
    cudaFuncSetAttribute(k_colfft, cudaFuncAttributeMaxDynamicSharedMemorySize, k2_smem);

    init_tw_kernel<<<1, 256>>>();
    k_rowfft<<<dim3(5, B), 384>>>(T2_Gen);
    k_colfft<<<dim3(8, B), 512, k2_smem>>>(underT2_K, A);
    k_invrow<<<dim3(15, B), 256>>>(out);
}

// round 14
// speedup vs baseline: 1.2395x; 1.0990x over previous
#include <cuda_runtime.h>
#include <cuda_fp16.h>
#include <math.h>

#define Hh 240
#define Ww 240
#define NPIX 57600           // 240*240
#define BMAX 256

// ---------------- scratch (no cudaMalloc allowed) ----------------
// g_s1h holds only the Hermitian-unique half: kw in [0,128)
__device__ __half2 g_s1h[BMAX * 128 * 240];  // after K1: [b][kw<128][h] (re,im) fp16
__device__ __half2 g_s2h[BMAX * NPIX];       // after K2: [b][h][kw]     (re,im) fp16
__device__ float2 g_tw[240];                 // forward twiddles e^{-2*pi*i*j/240}

// smem row v at offset 240*v + 2*(v>>1) (bank-conflict-free; R3 analysis)
#define SMF1 (24*242)          // K1 static smem floats per array (24 rows)
#define SMF3 (16*240 + 16)     // K3 static smem floats per array
#define SMF2 (32*240 + 32)     // K2 dynamic smem floats per array = 7712

__device__ __forceinline__ int rowoff(int v) { return 240 * v + 2 * (v >> 1); }

// ---------------- complex helpers ----------------
__device__ __forceinline__ float2 cadd(float2 a, float2 b){ return make_float2(a.x+b.x, a.y+b.y); }
__device__ __forceinline__ float2 csub(float2 a, float2 b){ return make_float2(a.x-b.x, a.y-b.y); }
__device__ __forceinline__ float2 cmul(float2 a, float2 b){
    return make_float2(a.x*b.x - a.y*b.y, a.x*b.y + a.y*b.x);
}

// DIR = -1 forward (e^{-i}), +1 inverse (e^{+i})
template<int DIR>
__device__ __forceinline__ void dft4(float2 a[4]) {
    float2 u0 = cadd(a[0], a[2]);
    float2 u1 = csub(a[0], a[2]);
    float2 u2 = cadd(a[1], a[3]);
    float2 u3 = csub(a[1], a[3]);
    float2 j3 = make_float2((DIR < 0) ? u3.y : -u3.y, (DIR < 0) ? -u3.x : u3.x);
    a[0] = cadd(u0, u2);
    a[2] = csub(u0, u2);
    a[1] = cadd(u1, j3);
    a[3] = csub(u1, j3);
}

__device__ __constant__ float C16c[10] = {1.f,0.92387953f,0.70710678f,0.38268343f,0.f,-0.38268343f,-0.70710678f,-0.92387953f,-1.f,-0.92387953f};
__device__ __constant__ float S16c[10] = {0.f,0.38268343f,0.70710678f,0.92387953f,1.f,0.92387953f,0.70710678f,0.38268343f,0.f,-0.38268343f};
__device__ __constant__ float C15c[9] = {1.f,0.91354546f,0.66913061f,0.30901699f,-0.10452846f,-0.5f,-0.80901699f,-0.97814760f,-0.97814760f};
__device__ __constant__ float S15c[9] = {0.f,0.40673664f,0.74314483f,0.95105652f,0.99452190f,0.86602540f,0.58778525f,0.20791169f,-0.20791169f};

template<int DIR>
__device__ __forceinline__ void fft16(float2 a[16]) {
    float2 b[4][4];
#pragma unroll
    for (int n2 = 0; n2 < 4; n2++) {
        float2 t[4];
#pragma unroll
        for (int n1 = 0; n1 < 4; n1++) t[n1] = a[4*n1 + n2];
        dft4<DIR>(t);
#pragma unroll
        for (int k1 = 0; k1 < 4; k1++) {
            const int j = n2 * k1;
            float2 w = make_float2(C16c[j], (DIR < 0) ? -S16c[j] : S16c[j]);
            b[n2][k1] = cmul(t[k1], w);
        }
    }
#pragma unroll
    for (int k1 = 0; k1 < 4; k1++) {
        float2 t[4];
#pragma unroll
        for (int n2 = 0; n2 < 4; n2++) t[n2] = b[n2][k1];
        dft4<DIR>(t);
#pragma unroll
        for (int k2 = 0; k2 < 4; k2++) a[k1 + 4*k2] = t[k2];
    }
}

template<int DIR>
__device__ __forceinline__ void dft5(float2 a[5]) {
    const float c1 = 0.309016994f, s1 = 0.951056516f;
    const float c2 = -0.809016994f, s2 = 0.587785252f;
    float2 a0 = a[0];
    float2 t1 = cadd(a[1], a[4]);
    float2 t2 = cadd(a[2], a[3]);
    float2 t3 = csub(a[1], a[4]);
    float2 t4 = csub(a[2], a[3]);
    float2 m1 = make_float2(a0.x + c1*t1.x + c2*t2.x, a0.y + c1*t1.y + c2*t2.y);
    float2 m2 = make_float2(a0.x + c2*t1.x + c1*t2.x, a0.y + c2*t1.y + c1*t2.y);
    float2 p1 = make_float2(s1*t3.x + s2*t4.x, s1*t3.y + s2*t4.y);
    float2 p2 = make_float2(s2*t3.x - s1*t4.x, s2*t3.y - s1*t4.y);
    float2 j1 = make_float2((DIR < 0) ? p1.y : -p1.y, (DIR < 0) ? -p1.x : p1.x);
    float2 j2 = make_float2((DIR < 0) ? p2.y : -p2.y, (DIR < 0) ? -p2.x : p2.x);
    a[0] = make_float2(a0.x + t1.x + t2.x, a0.y + t1.y + t2.y);
    a[1] = cadd(m1, j1);
    a[4] = csub(m1, j1);
    a[2] = cadd(m2, j2);
    a[3] = csub(m2, j2);
}

template<int DIR>
__device__ __forceinline__ void dft3(float2 a[3]) {
    const float s3 = 0.866025404f;
    float2 a0 = a[0];
    float2 t1 = cadd(a[1], a[2]);
    float2 t2 = csub(a[1], a[2]);
    float2 m = make_float2(a0.x - 0.5f*t1.x, a0.y - 0.5f*t1.y);
    float2 jt = make_float2((DIR < 0) ? s3*t2.y : -s3*t2.y, (DIR < 0) ? -s3*t2.x : s3*t2.x);
    a[0] = make_float2(a0.x + t1.x, a0.y + t1.y);
    a[1] = cadd(m, jt);
    a[2] = csub(m, jt);
}

template<int DIR>
__device__ __forceinline__ void fft15(float2 a[15]) {
    float2 c[3][5];
#pragma unroll
    for (int m2 = 0; m2 < 3; m2++) {
        float2 t[5];
#pragma unroll
        for (int m1 = 0; m1 < 5; m1++) t[m1] = a[3*m1 + m2];
        dft5<DIR>(t);
#pragma unroll
        for (int p1 = 0; p1 < 5; p1++) {
            const int j = m2 * p1;
            float2 w = make_float2(C15c[j], (DIR < 0) ? -S15c[j] : S15c[j]);
            c[m2][p1] = cmul(t[p1], w);
        }
    }
#pragma unroll
    for (int p1 = 0; p1 < 5; p1++) {
        float2 t[3] = {c[0][p1], c[1][p1], c[2][p1]};
        dft3<DIR>(t);
        a[p1]      = t[0];
        a[p1 + 5]  = t[1];
        a[p1 + 10] = t[2];
    }
}

// ---- stage pieces (warp-private rows; only __syncwarp) ----

template<int DIR>
__device__ __forceinline__ void stage1_tail(float2 a[16], float* re, float* im, int t) {
#pragma unroll
    for (int k1 = 1; k1 < 16; k1++) {
        float2 w = __ldg(&g_tw[t * k1]);
        if (DIR > 0) w.y = -w.y;
        a[k1] = cmul(a[k1], w);
    }
#pragma unroll
    for (int k1 = 0; k1 < 16; k1++) { re[15*k1 + t] = a[k1].x; im[15*k1 + t] = a[k1].y; }
}

template<int DIR>
__device__ __forceinline__ void stage1_s(float* re, float* im, int t) {
    if (t < 15) {
        float2 a[16];
#pragma unroll
        for (int n1 = 0; n1 < 16; n1++) { a[n1].x = re[15*n1 + t]; a[n1].y = im[15*n1 + t]; }
        fft16<DIR>(a);
        stage1_tail<DIR>(a, re, im, t);
    }
    __syncwarp();
}

// stage 1, complex fp16 inputs from global (L2-resident scratch, last use)
template<int DIR>
__device__ __forceinline__ void stage1_gh(const __half2* __restrict__ gsrc,
                                          float* re, float* im, int t) {
    if (t < 15) {
        float2 a[16];
#pragma unroll
        for (int n1 = 0; n1 < 16; n1++) a[n1] = __half22float2(__ldcs(&gsrc[15*n1 + t]));
        fft16<DIR>(a);
        stage1_tail<DIR>(a, re, im, t);
    }
    __syncwarp();
}

// stage 1, PACKED pair of real rows (a + i*b) loaded directly from global
__device__ __forceinline__ void stage1_g_pair(const float* __restrict__ ra,
                                              const float* __restrict__ rb,
                                              float* re, float* im, int t) {
    if (t < 15) {
        float2 a[16];
#pragma unroll
        for (int n1 = 0; n1 < 16; n1++)
            a[n1] = make_float2(__ldcs(&ra[15*n1 + t]), __ldcs(&rb[15*n1 + t]));
        fft16<-1>(a);
        stage1_tail<-1>(a, re, im, t);
    }
    __syncwarp();
}

template<int DIR>
__device__ __forceinline__ void stage2(float* re, float* im, int t) {
    float2 b[15];
#pragma unroll
    for (int n2 = 0; n2 < 15; n2++) { b[n2].x = re[15*t + n2]; b[n2].y = im[15*t + n2]; }
    fft15<DIR>(b);
    __syncwarp();
    const float sc = (DIR > 0) ? (1.0f / 240.0f) : 1.0f;
#pragma unroll
    for (int j = 0; j < 15; j++) { re[t + 16*j] = b[j].x * sc; im[t + 16*j] = b[j].y * sc; }
    __syncwarp();
}

// stage 2 inverse + magnitude, stored DIRECTLY to global (row-contiguous dst)
__device__ __forceinline__ void stage2_mag_g(const float* re, const float* im, int t,
                                             float* __restrict__ gdst) {
    float2 b[15];
#pragma unroll
    for (int n2 = 0; n2 < 15; n2++) { b[n2].x = re[15*t + n2]; b[n2].y = im[15*t + n2]; }
    fft15<1>(b);
    const float sc = 1.0f / 240.0f;
#pragma unroll
    for (int j = 0; j < 15; j++)
        gdst[t + 16*j] = sc * sqrtf(b[j].x * b[j].x + b[j].y * b[j].y);
}

// ---------------- kernels ----------------
__global__ void init_tw_kernel() {
    int j = threadIdx.x;
    if (j < 240) {
        float s, c;
        sincosf(-6.283185307179586f * (float)j / 240.0f, &s, &c);
        g_tw[j] = make_float2(c, s);
    }
}

// K1: packed forward row FFTs of real input -> g_s1h[b][kw<128][h]
// 384 threads, 12 warps; warp w does packed FFTs p=2w (h=0) and p=2w+1 (h=1);
// packed FFT p covers real rows (h0+2p, h0+2p+1).  grid.x = 5 (48 rows/block).
__global__ __launch_bounds__(384) void k_rowfft(const float* __restrict__ x) {
    __shared__ float sre[SMF1], sim[SMF1];
    const int b = blockIdx.y;
    const int h0 = blockIdx.x * 48;
    const int tid = threadIdx.x;
    const int w = tid >> 5, lane = tid & 31;
    const int t = lane & 15, h = lane >> 4;
    const int p = 2 * w + h;                 // packed index 0..23

    const float* ra = x + ((size_t)b * 240 + h0 + 2 * p) * 240;
    float* re = sre + 482 * w + 240 * h;     // == sre + rowoff(p)
    float* im = sim + 482 * w + 240 * h;
    stage1_g_pair(ra, ra + 240, re, im, t);
    stage2<-1>(re, im, t);
    __syncthreads();

    // separation + transposed fp16 store: Z = FFT(a+ib) ->
    //   A[k] = (Z[k]+conj(Z[m]))/2,  B[k] = -i(Z[k]-conj(Z[m]))/2,  m=(240-k)%240
    {
        const int hh = tid % 48;
        const int kwb = tid / 48;            // 0..7
        const int pp = hh >> 1, e = hh & 1;
        const float* zr = sre + rowoff(pp);
        const float* zi = sim + rowoff(pp);
        __half2* dst = g_s1h + ((size_t)b * 128) * 240 + h0 + hh;
#pragma unroll
        for (int jj = 0; jj < 16; jj++) {
            int kw = kwb * 16 + jj;          // 0..127
            int m = (kw == 0) ? 0 : 240 - kw;
            float x1 = zr[kw], y1 = zi[kw];
            float x2 = zr[m],  y2 = zi[m];
            float2 v;
            if (e == 0) v = make_float2(0.5f * (x1 + x2), 0.5f * (y1 - y2));
            else        v = make_float2(0.5f * (y1 + y2), 0.5f * (x2 - x1));
            dst[(size_t)kw * 240] = __floats2half2_rn(v.x, v.y);
        }
    }
}

// K2: fwd column FFT of 16 primary cols (warps 0-7, deduped) + Hermitian mirror
// reconstruction + combine + 32 column IFFTs (all 16 warps).  512 threads.
__global__ __launch_bounds__(512, 2) void k_colfft(const float* __restrict__ yk,
                                                   const float* __restrict__ Am) {
    extern __shared__ float dsm[];
    float* sre = dsm;
    float* sim = dsm + SMF2;
    const int b = blockIdx.y;
    const int kw0 = blockIdx.x * 16;     // blockIdx.x in [0,8) -> primaries 0..127
    const int tid = threadIdx.x;
    const int w = tid >> 5, lane = tid & 31;
    const int t = lane & 15;
    const int h = lane >> 4;

    // ---- forward FFT of 16 primary columns: warps 0-7 own rows 2w, 2w+1;
    // warps 8-15 go straight to the barrier (no duplicated loads/FLOPs) ----
    if (w < 8) {
        const int row = 2 * w + h;
        float* re = sre + rowoff(row);
        float* im = sim + rowoff(row);
        const __half2* gsrc = g_s1h + ((size_t)b * 128 + kw0 + row) * 240;
        stage1_gh<-1>(gsrc, re, im, t);      // L2 hits from K1's fresh stores
        stage2<-1>(re, im, t);
    }
    __syncthreads();

    const float* yr = yk + (size_t)b * (2 * NPIX);
    const float* yi = yr + NPIX;

    // ---- mirror build + combine: row 16+v <- (1-A')*conj(rev(row v)) + y' ----
    {
        const int v = tid & 15;
        const int khb = tid >> 4;            // 0..31
        const int kwm = (240 - (kw0 + v)) % 240;
        const float* pre = sre + rowoff(v);
        const float* pim = sim + rowoff(v);
        float* mre = sre + rowoff(16 + v);
        float* mim = sim + rowoff(16 + v);
#pragma unroll
        for (int j = 0; j < 8; j++) {
            int kh = khb + 32 * j;
            if (kh < 240) {
                int s = (kh == 0) ? 0 : 240 - kh;
                int idx = kh * 240 + kwm;
                float a = 1.0f - __ldg(&Am[idx]);
                mre[kh] =  pre[s] * a + __ldcs(&yr[idx]);
                mim[kh] = -pim[s] * a + __ldcs(&yi[idx]);
            }
        }
    }
    __syncthreads();

    // ---- primary combine in place ----
    {
        const int v = tid & 15;
        const int khb = tid >> 4;
        float* pre = sre + rowoff(v);
        float* pim = sim + rowoff(v);
#pragma unroll
        for (int j = 0; j < 8; j++) {
            int kh = khb + 32 * j;
            if (kh < 240) {
                int idx = kh * 240 + kw0 + v;
                float a = 1.0f - __ldg(&Am[idx]);
                pre[kh] = pre[kh] * a + __ldcs(&yr[idx]);
                pim[kh] = pim[kh] * a + __ldcs(&yi[idx]);
            }
        }
    }
    __syncthreads();

    // ---- inverse FFT of all 32 rows: warp w owns rows 2w, 2w+1 ----
    {
        const int v = 2 * w + h;
        float* re = sre + rowoff(v);
        float* im = sim + rowoff(v);
        stage1_s<1>(re, im, t);
        stage2<1>(re, im, t);
    }
    __syncthreads();

    // ---- transposed fp16 store: primaries always; mirrors only if kwm >= 128
    // (masks the redundant overlap -> each g_s2h word written exactly once) ----
    {
        const int v = tid & 15;
        const int hb = tid >> 4;             // 0..31
        const float* pre = sre + rowoff(v);
        const float* pim = sim + rowoff(v);
        const float* mre = sre + rowoff(16 + v);
        const float* mim = sim + rowoff(16 + v);
        const int kwm = (240 - (kw0 + v)) % 240;
        __half2* dstP = g_s2h + (size_t)b * NPIX + kw0 + v;
        __half2* dstM = g_s2h + (size_t)b * NPIX + kwm;
        const bool storeM = (kwm >= 128);
#pragma unroll
        for (int j = 0; j < 8; j++) {
            int hh = hb + 32 * j;
            if (hh < 240) {
                dstP[(size_t)hh * 240] = __floats2half2_rn(pre[hh], pim[hh]);
                if (storeM) dstM[(size_t)hh * 240] = __floats2half2_rn(mre[hh], mim[hh]);
            }
        }
    }
}

// K3: inverse row FFTs + abs -> out[b][h][w]  (zero staging, no block sync)
__global__ __launch_bounds__(256) void k_invrow(float* __restrict__ out) {
    __shared__ float sre[SMF3], sim[SMF3];
    const int b = blockIdx.y;
    const int h0 = blockIdx.x * 16;
    const int tid = threadIdx.x;
    const int w = tid >> 5, lane = tid & 31;
    const int t = lane & 15, h = lane >> 4;

    float* re = sre + 482 * w + 240 * h;
    float* im = sim + 482 * w + 240 * h;

    const __half2* gsrc = g_s2h + ((size_t)b * 240 + h0 + 2 * w + h) * 240;
    stage1_gh<1>(gsrc, re, im, t);           // L2-resident fp16, last use

    float* ob = out + ((size_t)b * 240 + h0 + 2 * w + h) * 240;
    stage2_mag_g(re, im, t, ob);
}

extern "C" void kernel_launch(void* const* d_in, const int* in_sizes, int n_in,
                              void* d_out, int out_size) {
    const float* T2_Gen    = (const float*)d_in[0];  // [B,1,240,240] f32
    const float* underT2_K = (const float*)d_in[1];  // [B,2,240,240] f32
    const float* A         = (const float*)d_in[2];  // [240,240] f32
    float* out = (float*)d_out;

    int B = in_sizes[0] / NPIX;   // 256

    const int k2_smem = 2 * SMF2 * (int)sizeof(float);   // 61,696 B
    cudaFuncSetAttribute(k_colfft, cudaFuncAttributeMaxDynamicSharedMemorySize, k2_smem);

    init_tw_kernel<<<1, 256>>>();
    k_rowfft<<<dim3(5, B), 384>>>(T2_Gen);
    k_colfft<<<dim3(8, B), 512, k2_smem>>>(underT2_K, A);
    k_invrow<<<dim3(15, B), 256>>>(out);
}